// round 2
// baseline (speedup 1.0000x reference)
#include <cuda_runtime.h>

// MoEGate: logits = X[T,H] @ W[E,H]^T ; top-8 of logits; softmax over the 8; renorm.
// T=16384, H=2048, E=64, K=8.
// Output (float32): [T*8] topk weights, then [T*8] topk indices (as float).

#define H_DIM 2048
#define N_EXP 64
#define TOPK  8

#define BM 128
#define BN 64
#define BK 64
#define NTILES (H_DIM / BK)          // 32
#define NTHREADS 256

#define XS_STRIDE (BM + 4)           // 132 floats = 528B (16B-aligned rows)
#define XS_BYTES  (2 * BK * XS_STRIDE * 4)   // 67584
#define WS_BYTES  (2 * BK * BN * 8)          // 65536 (duplicated f32x2 pairs)
#define SMEM_BYTES (XS_BYTES + WS_BYTES)     // 133120

typedef unsigned long long u64;

__device__ __forceinline__ u64 ffma2(u64 a, u64 b, u64 c) {
    u64 d;
    asm("fma.rn.f32x2 %0, %1, %2, %3;" : "=l"(d) : "l"(a), "l"(b), "l"(c));
    return d;
}

__device__ __forceinline__ u64 pack2(float lo, float hi) {
    u64 r;
    asm("mov.b64 %0, {%1, %2};" : "=l"(r) : "f"(lo), "f"(hi));
    return r;
}

__device__ __forceinline__ void unpack2(u64 v, float& lo, float& hi) {
    asm("mov.b64 {%0, %1}, %2;" : "=f"(lo), "=f"(hi) : "l"(v));
}

__global__ __launch_bounds__(NTHREADS, 1)
void moe_gate_kernel(const float* __restrict__ X,   // [T, H]
                     const float* __restrict__ W,   // [E, H]
                     float* __restrict__ out,       // [T*8 w][T*8 idx]
                     int T) {
    extern __shared__ char smem_raw[];
    float* Xs  = reinterpret_cast<float*>(smem_raw);              // [2][BK][XS_STRIDE]
    u64*   Wsd = reinterpret_cast<u64*>(smem_raw + XS_BYTES);     // [2][BK][BN]
    float (*logits)[N_EXP + 1] =
        reinterpret_cast<float(*)[N_EXP + 1]>(smem_raw);          // aliases Xs buf0

    const int tid = threadIdx.x;
    const int tx = tid & 15;          // experts tx*4 .. tx*4+3
    const int ty = tid >> 4;          // tokens  ty*8 .. ty*8+7
    const int block_m = blockIdx.x * BM;

    // global-load mapping
    const int xrow  = tid >> 1;           // 0..127 token within block
    const int xcol0 = (tid & 1) * 32;     // 0 / 32
    const int wrow  = tid >> 2;           // 0..63 expert
    const int wcol0 = (tid & 3) * 16;     // 0,16,32,48

    const float* Xg = X + (long long)(block_m + xrow) * H_DIM + xcol0;
    const float* Wg = W + (long long)wrow * H_DIM + wcol0;

    // acc[expert j][token-pair i]: f32x2 over tokens (ty*8+2i, ty*8+2i+1)
    u64 acc[4][4];
#pragma unroll
    for (int j = 0; j < 4; j++)
#pragma unroll
        for (int i = 0; i < 4; i++) acc[j][i] = 0ull;

    float4 xreg[8];
    float4 wreg[4];

    // prefetch tile 0
#pragma unroll
    for (int q = 0; q < 8; q++) xreg[q] = *reinterpret_cast<const float4*>(Xg + 4 * q);
#pragma unroll
    for (int q = 0; q < 4; q++) wreg[q] = *reinterpret_cast<const float4*>(Wg + 4 * q);

    for (int t = 0; t < NTILES; ++t) {
        const int buf = t & 1;
        float* xs = Xs + buf * (BK * XS_STRIDE);
        u64*   ws = Wsd + buf * (BK * BN);

        // ---- store prefetched regs to smem ----
        // X transposed: xs[k][m]
#pragma unroll
        for (int q = 0; q < 8; q++) {
            const int c = xcol0 + 4 * q;
            xs[(c + 0) * XS_STRIDE + xrow] = xreg[q].x;
            xs[(c + 1) * XS_STRIDE + xrow] = xreg[q].y;
            xs[(c + 2) * XS_STRIDE + xrow] = xreg[q].z;
            xs[(c + 3) * XS_STRIDE + xrow] = xreg[q].w;
        }
        // W transposed + duplicated pairs: ws[k][e] = (w,w)
#pragma unroll
        for (int q = 0; q < 4; q++) {
            const int c = wcol0 + 4 * q;
            ws[(c + 0) * BN + wrow] = pack2(wreg[q].x, wreg[q].x);
            ws[(c + 1) * BN + wrow] = pack2(wreg[q].y, wreg[q].y);
            ws[(c + 2) * BN + wrow] = pack2(wreg[q].z, wreg[q].z);
            ws[(c + 3) * BN + wrow] = pack2(wreg[q].w, wreg[q].w);
        }
        __syncthreads();   // single barrier per tile (store -> sync -> compute)

        // ---- prefetch next tile ----
        if (t + 1 < NTILES) {
            const float* xg = Xg + (t + 1) * BK;
            const float* wg = Wg + (t + 1) * BK;
#pragma unroll
            for (int q = 0; q < 8; q++)
                xreg[q] = *reinterpret_cast<const float4*>(xg + 4 * q);
#pragma unroll
            for (int q = 0; q < 4; q++)
                wreg[q] = *reinterpret_cast<const float4*>(wg + 4 * q);
        }

        // ---- compute BK k-steps, all LDS.128, zero packing ----
        const float* xk = xs + ty * 8;
        const u64*   wk = ws + tx * 4;
#pragma unroll 8
        for (int k = 0; k < BK; ++k) {
            ulonglong2 xa = *reinterpret_cast<const ulonglong2*>(xk + (size_t)k * XS_STRIDE);
            ulonglong2 xb = *reinterpret_cast<const ulonglong2*>(xk + (size_t)k * XS_STRIDE + 4);
            ulonglong2 wa = *reinterpret_cast<const ulonglong2*>(wk + (size_t)k * BN);
            ulonglong2 wb = *reinterpret_cast<const ulonglong2*>(wk + (size_t)k * BN + 2);
            u64 xv[4] = {xa.x, xa.y, xb.x, xb.y};
            u64 wv[4] = {wa.x, wa.y, wb.x, wb.y};
#pragma unroll
            for (int j = 0; j < 4; ++j)
#pragma unroll
                for (int i = 0; i < 4; ++i)
                    acc[j][i] = ffma2(xv[i], wv[j], acc[j][i]);
        }
        // no second barrier needed: next iter stores to the other buffer, and
        // the sync above already ordered all warps past compute(t-1).
    }

    __syncthreads();   // all compute done before logits (aliased to Xs buf0) writes

    // write logits tile to smem
#pragma unroll
    for (int j = 0; j < 4; j++) {
#pragma unroll
        for (int i = 0; i < 4; i++) {
            float lo, hi;
            unpack2(acc[j][i], lo, hi);
            logits[ty * 8 + 2 * i + 0][tx * 4 + j] = lo;
            logits[ty * 8 + 2 * i + 1][tx * 4 + j] = hi;
        }
    }
    __syncthreads();

    // fused epilogue: top-8 of logits (== top-8 of softmax since softmax is
    // monotone), then softmax over the selected 8 (global denominator cancels
    // under the top-k renormalization).
    if (tid < BM) {
        float* row = logits[tid];
        float vals[TOPK];
        int   idxs[TOPK];
#pragma unroll
        for (int r = 0; r < TOPK; r++) {
            float best = -__int_as_float(0x7f800000);  // -inf
            int bi = 0;
            for (int e = 0; e < N_EXP; e++) {
                float v = row[e];
                if (v > best) { best = v; bi = e; }   // strict '>' => lowest index on ties
            }
            vals[r] = best;
            idxs[r] = bi;
            row[bi] = -__int_as_float(0x7f800000);
        }
        const float m0 = vals[0];
        float w[TOPK];
        float s = 0.f;
#pragma unroll
        for (int r = 0; r < TOPK; r++) { w[r] = __expf(vals[r] - m0); s += w[r]; }
        const float inv = 1.f / s;

        const long long gtok = block_m + tid;
#pragma unroll
        for (int r = 0; r < TOPK; r++) {
            out[gtok * TOPK + r] = w[r] * inv;
            out[(long long)T * TOPK + gtok * TOPK + r] = (float)idxs[r];
        }
    }
}

extern "C" void kernel_launch(void* const* d_in, const int* in_sizes, int n_in,
                              void* d_out, int out_size) {
    const float* X = (const float*)d_in[0];   // hidden_states [4,4096,2048] fp32
    const float* W = (const float*)d_in[1];   // weight [64,2048] fp32
    float* out = (float*)d_out;

    const int T = in_sizes[0] / H_DIM;        // 16384
    const int grid = T / BM;                  // 128

    cudaFuncSetAttribute(moe_gate_kernel,
                         cudaFuncAttributeMaxDynamicSharedMemorySize, SMEM_BYTES);
    moe_gate_kernel<<<grid, NTHREADS, SMEM_BYTES>>>(X, W, out, T);
}

// round 5
// speedup vs baseline: 1.3649x; 1.3649x over previous
#include <cuda_runtime.h>
#include <cstdint>

// MoEGate: logits = X[T,2048] @ W[64,2048]^T in fp32 (sequential-k accumulation,
// error-correlated with the fp32 reference), then top-8 of logits (== top-8 of
// softmax), softmax over the selected 8, renormalize.
// Output (float32): [T*8] topk weights, then [T*8] topk indices (as float).

#define H_DIM 2048
#define N_EXP 64
#define TOPK  8
#define BM    128
#define BK    32
#define KTILES (H_DIM / BK)      // 64
#define NTHREADS 128

// smem: Xs[2][BK][128] fp32 (2*16KB) then Ws[2][BK][64] u64 dup-pairs (2*16KB)
#define XS_OFF   0
#define XS_TILE  (BK * BM * 4)          // 16384
#define WS_OFF   (2 * XS_TILE)          // 32768
#define WS_TILE  (BK * N_EXP * 8)       // 16384
#define SMEM_BYTES (WS_OFF + 2 * WS_TILE)   // 65536

typedef unsigned long long u64;

static __device__ __forceinline__ u64 ffma2(u64 a, u64 b, u64 c) {
    u64 d;
    asm("fma.rn.f32x2 %0, %1, %2, %3;" : "=l"(d) : "l"(a), "l"(b), "l"(c));
    return d;
}
static __device__ __forceinline__ void unpack2(u64 v, float& lo, float& hi) {
    asm("mov.b64 {%0, %1}, %2;" : "=f"(lo), "=f"(hi) : "l"(v));
}

__global__ __launch_bounds__(NTHREADS, 1)
void moe_gate_kernel(const float* __restrict__ X,   // [T, H]
                     const float* __restrict__ W,   // [E, H]
                     float* __restrict__ out,       // [T*8 w][T*8 idx]
                     int T) {
    extern __shared__ char smem_raw[];
    float* XsAll = reinterpret_cast<float*>(smem_raw + XS_OFF);
    u64*   WsAll = reinterpret_cast<u64*>(smem_raw + WS_OFF);

    const int tid  = threadIdx.x;
    const int lane = tid & 31;
    const int wid  = tid >> 5;
    const int block_m = blockIdx.x * BM;

    // compute mapping: thread owns tokens ty*8..ty*8+7, experts e0..e0+7
    const int ty = lane & 15;
    const int e0 = wid * 16 + (lane >> 4) * 8;

    // global-load mapping
    // X: thread loads token (block_m + tid), 32 k per tile (8 float4)
    const float* Xg = X + (size_t)(block_m + tid) * H_DIM;
    // W: lane -> experts 2*lane, 2*lane+1 ; warp wid -> k-offset wid*8 (8 k each)
    const int k8 = wid * 8;
    const float* Wg0 = W + (size_t)(2 * lane + 0) * H_DIM + k8;
    const float* Wg1 = W + (size_t)(2 * lane + 1) * H_DIM + k8;

    // acc[expert j][token-pair i]
    u64 acc[8][4];
#pragma unroll
    for (int j = 0; j < 8; j++)
#pragma unroll
        for (int i = 0; i < 4; i++) acc[j][i] = 0ull;

    float4 xreg[8];   // 32 k of own token
    float4 wreg[4];   // 2 experts x 8 k

    // prefetch tile 0
#pragma unroll
    for (int q = 0; q < 8; q++) xreg[q] = *reinterpret_cast<const float4*>(Xg + 4 * q);
    wreg[0] = *reinterpret_cast<const float4*>(Wg0);
    wreg[1] = *reinterpret_cast<const float4*>(Wg0 + 4);
    wreg[2] = *reinterpret_cast<const float4*>(Wg1);
    wreg[3] = *reinterpret_cast<const float4*>(Wg1 + 4);

    for (int t = 0; t < KTILES; ++t) {
        const int buf = t & 1;
        float* xs = XsAll + buf * (XS_TILE / 4);
        u64*   ws = WsAll + buf * (WS_TILE / 8);

        // ---- store prefetched regs (transposed) ----
        // X: xs[k][tid]  (lanes -> consecutive banks, conflict-free)
#pragma unroll
        for (int q = 0; q < 8; q++) {
            xs[(4 * q + 0) * BM + tid] = xreg[q].x;
            xs[(4 * q + 1) * BM + tid] = xreg[q].y;
            xs[(4 * q + 2) * BM + tid] = xreg[q].z;
            xs[(4 * q + 3) * BM + tid] = xreg[q].w;
        }
        // W: ws[k][e] = (w,w) pairs; store 2 experts' pair as one 16B STS
        {
            const float* wf = reinterpret_cast<const float*>(wreg);   // [2][8] k-major
            float4* wrow = reinterpret_cast<float4*>(ws);             // [BK][32] float4
#pragma unroll
            for (int kk = 0; kk < 8; kk++) {
                float a = wf[kk];       // expert 2*lane
                float b = wf[8 + kk];   // expert 2*lane+1
                wrow[(k8 + kk) * 32 + lane] = make_float4(a, a, b, b);
            }
        }
        __syncthreads();   // single barrier per tile (store -> sync -> compute)

        // ---- prefetch next tile into regs ----
        if (t + 1 < KTILES) {
            const float* xg = Xg + (t + 1) * BK;
#pragma unroll
            for (int q = 0; q < 8; q++)
                xreg[q] = *reinterpret_cast<const float4*>(xg + 4 * q);
            const float* wg0 = Wg0 + (t + 1) * BK;
            const float* wg1 = Wg1 + (t + 1) * BK;
            wreg[0] = *reinterpret_cast<const float4*>(wg0);
            wreg[1] = *reinterpret_cast<const float4*>(wg0 + 4);
            wreg[2] = *reinterpret_cast<const float4*>(wg1);
            wreg[3] = *reinterpret_cast<const float4*>(wg1 + 4);
        }

        // ---- compute BK k-steps with frag double-buffering ----
        const u64* xk = reinterpret_cast<const u64*>(xs) + ty * 4;   // 4 token-pairs
        const u64* wk = ws + e0;                                     // 8 expert-pairs

        u64 fx[2][4], fw[2][8];
        // load frag k=0
        {
            ulonglong2 a = *reinterpret_cast<const ulonglong2*>(xk);
            ulonglong2 b = *reinterpret_cast<const ulonglong2*>(xk + 2);
            fx[0][0] = a.x; fx[0][1] = a.y; fx[0][2] = b.x; fx[0][3] = b.y;
            ulonglong2 w0 = *reinterpret_cast<const ulonglong2*>(wk);
            ulonglong2 w1 = *reinterpret_cast<const ulonglong2*>(wk + 2);
            ulonglong2 w2 = *reinterpret_cast<const ulonglong2*>(wk + 4);
            ulonglong2 w3 = *reinterpret_cast<const ulonglong2*>(wk + 6);
            fw[0][0] = w0.x; fw[0][1] = w0.y; fw[0][2] = w1.x; fw[0][3] = w1.y;
            fw[0][4] = w2.x; fw[0][5] = w2.y; fw[0][6] = w3.x; fw[0][7] = w3.y;
        }
#pragma unroll
        for (int k = 0; k < BK; k++) {
            const int cur = k & 1, nxt = cur ^ 1;
            if (k + 1 < BK) {   // prefetch frag k+1
                const u64* xn = xk + (size_t)(k + 1) * (BM / 2);
                const u64* wn = wk + (size_t)(k + 1) * N_EXP;
                ulonglong2 a = *reinterpret_cast<const ulonglong2*>(xn);
                ulonglong2 b = *reinterpret_cast<const ulonglong2*>(xn + 2);
                fx[nxt][0] = a.x; fx[nxt][1] = a.y; fx[nxt][2] = b.x; fx[nxt][3] = b.y;
                ulonglong2 w0 = *reinterpret_cast<const ulonglong2*>(wn);
                ulonglong2 w1 = *reinterpret_cast<const ulonglong2*>(wn + 2);
                ulonglong2 w2 = *reinterpret_cast<const ulonglong2*>(wn + 4);
                ulonglong2 w3 = *reinterpret_cast<const ulonglong2*>(wn + 6);
                fw[nxt][0] = w0.x; fw[nxt][1] = w0.y; fw[nxt][2] = w1.x; fw[nxt][3] = w1.y;
                fw[nxt][4] = w2.x; fw[nxt][5] = w2.y; fw[nxt][6] = w3.x; fw[nxt][7] = w3.y;
            }
#pragma unroll
            for (int j = 0; j < 8; j++)
#pragma unroll
                for (int i = 0; i < 4; i++)
                    acc[j][i] = ffma2(fx[cur][i], fw[cur][j], acc[j][i]);
        }
        // next iter stores to the other buffer; its sync orders reuse (proof: a
        // store at t+2 follows sync(t+1), which follows every warp's compute(t)).
    }

    __syncthreads();   // compute done everywhere before logits alias smem

    // logits[128][66]
    float* lg = reinterpret_cast<float*>(smem_raw);
#pragma unroll
    for (int j = 0; j < 8; j++)
#pragma unroll
        for (int i = 0; i < 4; i++) {
            float lo, hi;
            unpack2(acc[j][i], lo, hi);
            lg[(ty * 8 + 2 * i + 0) * 66 + e0 + j] = lo;
            lg[(ty * 8 + 2 * i + 1) * 66 + e0 + j] = hi;
        }
    __syncthreads();

    // fused top-8 + softmax over the 8 (global softmax denominator cancels
    // under renormalization; softmax is monotone so top-8 of logits == top-8
    // of softmax).
    {
        float* row = lg + tid * 66;
        float vals[TOPK];
        int   idxs[TOPK];
#pragma unroll
        for (int r = 0; r < TOPK; r++) {
            float best = -__int_as_float(0x7f800000);
            int bi = 0;
            for (int e = 0; e < N_EXP; e++) {
                float v = row[e];
                if (v > best) { best = v; bi = e; }   // strict '>' => lowest index on ties
            }
            vals[r] = best;
            idxs[r] = bi;
            row[bi] = -__int_as_float(0x7f800000);
        }
        const float m0 = vals[0];
        float wv[TOPK];
        float s = 0.f;
#pragma unroll
        for (int r = 0; r < TOPK; r++) { wv[r] = __expf(vals[r] - m0); s += wv[r]; }
        const float inv = 1.f / s;

        const long long gtok = block_m + tid;
#pragma unroll
        for (int r = 0; r < TOPK; r++) {
            out[gtok * TOPK + r] = wv[r] * inv;
            out[(long long)T * TOPK + gtok * TOPK + r] = (float)idxs[r];
        }
    }
}

extern "C" void kernel_launch(void* const* d_in, const int* in_sizes, int n_in,
                              void* d_out, int out_size) {
    const float* X = (const float*)d_in[0];   // hidden_states [4,4096,2048] fp32
    const float* W = (const float*)d_in[1];   // weight [64,2048] fp32
    float* out = (float*)d_out;

    const int T = in_sizes[0] / H_DIM;        // 16384
    const int grid = T / BM;                  // 128

    cudaFuncSetAttribute(moe_gate_kernel,
                         cudaFuncAttributeMaxDynamicSharedMemorySize, SMEM_BYTES);
    moe_gate_kernel<<<grid, NTHREADS, SMEM_BYTES>>>(X, W, out, T);
}

// round 6
// speedup vs baseline: 1.6032x; 1.1746x over previous
#include <cuda_runtime.h>
#include <cstdint>

// MoEGate hybrid:
//  1) fast path: logits via mma.sync tf32 3-split (Ootomo) -> top-9 -> if all
//     adjacent gaps >= EPS, ranking is provably fp32-robust -> emit.
//  2) ambiguous tokens (tiny gap) go to a slow list; fixup kernel recomputes
//     them with strict sequential-k fp32 (reference-matching order, proven in R1).
// Output (float32): [T*8] topk weights, then [T*8] topk indices (as float).

#define H_DIM 2048
#define N_EXP 64
#define TOPK  8
#define BM    128
#define BN    64
#define BK    32
#define KTILES (H_DIM / BK)         // 64
#define NTHREADS 256
#define NSTAGE 3
#define EPS   2e-4f

#define XS_BYTES (BM * BK * 4)
#define WS_BYTES (BN * BK * 4)
#define STAGE_BYTES (XS_BYTES + WS_BYTES)
#define SMEM_BYTES (NSTAGE * STAGE_BYTES)

__device__ int g_slow_count;
__device__ int g_slow_tokens[16384];

static __device__ __forceinline__ uint32_t smem_u32(const void* p) {
    uint32_t a;
    asm("{ .reg .u64 t; cvta.to.shared.u64 t, %1; cvt.u32.u64 %0, t; }" : "=r"(a) : "l"(p));
    return a;
}
static __device__ __forceinline__ uint32_t swz(uint32_t off) { return off ^ ((off >> 3) & 0x70); }

static __device__ __forceinline__ void cp16(uint32_t dst, const void* src) {
    asm volatile("cp.async.cg.shared.global [%0], [%1], 16;" :: "r"(dst), "l"(src) : "memory");
}
static __device__ __forceinline__ void ldsm4(uint32_t r[4], uint32_t addr) {
    asm volatile("ldmatrix.sync.aligned.m8n8.x4.shared.b16 {%0,%1,%2,%3}, [%4];"
                 : "=r"(r[0]), "=r"(r[1]), "=r"(r[2]), "=r"(r[3]) : "r"(addr));
}
static __device__ __forceinline__ void split_tf32(uint32_t raw, uint32_t& hi, uint32_t& lo) {
    float x = __uint_as_float(raw);
    uint32_t h;
    asm("cvt.rna.tf32.f32 %0, %1;" : "=r"(h) : "f"(x));
    float l = x - __uint_as_float(h);
    asm("cvt.rna.tf32.f32 %0, %1;" : "=r"(lo) : "f"(l));
    hi = h;
}
static __device__ __forceinline__ void mma8(float c[4], const uint32_t a[4], const uint32_t b[2]) {
    asm volatile(
        "mma.sync.aligned.m16n8k8.row.col.f32.tf32.tf32.f32 "
        "{%0,%1,%2,%3}, {%4,%5,%6,%7}, {%8,%9}, {%0,%1,%2,%3};"
        : "+f"(c[0]), "+f"(c[1]), "+f"(c[2]), "+f"(c[3])
        : "r"(a[0]), "r"(a[1]), "r"(a[2]), "r"(a[3]), "r"(b[0]), "r"(b[1]));
}

__global__ void reset_kernel() { g_slow_count = 0; }

__global__ __launch_bounds__(NTHREADS, 1)
void moe_gate_fast(const float* __restrict__ X, const float* __restrict__ W,
                   float* __restrict__ out, int T) {
    extern __shared__ char smem_raw[];
    const uint32_t sbase = smem_u32(smem_raw);
    const int tid = threadIdx.x;
    const int block_m = blockIdx.x * BM;

    const int xr[4] = {(tid + 0) >> 3, (tid + 256) >> 3, (tid + 512) >> 3, (tid + 768) >> 3};
    const int xc[4] = {(tid + 0) & 7, (tid + 256) & 7, (tid + 512) & 7, (tid + 768) & 7};
    const int wr[2] = {(tid + 0) >> 3, (tid + 256) >> 3};
    const int wc[2] = {(tid + 0) & 7, (tid + 256) & 7};

    auto issue_tile = [&](int t) {
        const uint32_t sb = sbase + (uint32_t)(t % NSTAGE) * STAGE_BYTES;
        const int kt = t * BK;
#pragma unroll
        for (int q = 0; q < 4; q++) {
            uint32_t dst = sb + swz((uint32_t)xr[q] * 128 + (uint32_t)xc[q] * 16);
            cp16(dst, X + (size_t)(block_m + xr[q]) * H_DIM + kt + xc[q] * 4);
        }
#pragma unroll
        for (int q = 0; q < 2; q++) {
            uint32_t dst = sb + XS_BYTES + swz((uint32_t)wr[q] * 128 + (uint32_t)wc[q] * 16);
            cp16(dst, W + (size_t)wr[q] * H_DIM + kt + wc[q] * 4);
        }
        asm volatile("cp.async.commit_group;" ::: "memory");
    };

    const int wid = tid >> 5;
    const int lane = tid & 31;
    const int m0 = (wid & 3) * 32;
    const int n0 = (wid >> 2) * 32;
    const int gid = lane >> 2;
    const int tig = lane & 3;

    const uint32_t a_off0 = (uint32_t)(m0 + (lane & 15)) * 128 + ((uint32_t)(lane >> 4) << 4);
    uint32_t b_off[2];
#pragma unroll
    for (int p = 0; p < 2; p++)
        b_off[p] = (uint32_t)(n0 + 8 * (2 * p + (lane >> 4)) + (lane & 7)) * 128 +
                   (((uint32_t)(lane >> 3) & 1u) << 4);

    float acc[2][4][4];
#pragma unroll
    for (int mt = 0; mt < 2; mt++)
#pragma unroll
        for (int nf = 0; nf < 4; nf++)
#pragma unroll
            for (int r = 0; r < 4; r++) acc[mt][nf][r] = 0.f;

#pragma unroll
    for (int s = 0; s < NSTAGE - 1; s++) issue_tile(s);

    for (int t = 0; t < KTILES; t++) {
        asm volatile("cp.async.wait_group %0;" :: "n"(NSTAGE - 2) : "memory");
        __syncthreads();

        if (t + NSTAGE - 1 < KTILES) issue_tile(t + NSTAGE - 1);
        else asm volatile("cp.async.commit_group;" ::: "memory");

        const uint32_t xb = sbase + (uint32_t)(t % NSTAGE) * STAGE_BYTES;
        const uint32_t wb = xb + XS_BYTES;

#pragma unroll
        for (int s8 = 0; s8 < 4; s8++) {
            const uint32_t ko = (uint32_t)s8 * 32;

            uint32_t araw[2][4], ahi[2][4], alo[2][4];
            ldsm4(araw[0], xb + swz(a_off0 + ko));
            ldsm4(araw[1], xb + swz(a_off0 + 2048 + ko));
#pragma unroll
            for (int mt = 0; mt < 2; mt++)
#pragma unroll
                for (int r = 0; r < 4; r++)
                    split_tf32(araw[mt][r], ahi[mt][r], alo[mt][r]);

            uint32_t braw[2][4], bhi[4][2], blo[4][2];
            ldsm4(braw[0], wb + swz(b_off[0] + ko));
            ldsm4(braw[1], wb + swz(b_off[1] + ko));
#pragma unroll
            for (int p = 0; p < 2; p++)
#pragma unroll
                for (int j = 0; j < 2; j++) {
                    split_tf32(braw[p][2 * j + 0], bhi[2 * p + j][0], blo[2 * p + j][0]);
                    split_tf32(braw[p][2 * j + 1], bhi[2 * p + j][1], blo[2 * p + j][1]);
                }

#pragma unroll
            for (int mt = 0; mt < 2; mt++)
#pragma unroll
                for (int nf = 0; nf < 4; nf++) {
                    mma8(acc[mt][nf], ahi[mt], bhi[nf]);
                    mma8(acc[mt][nf], ahi[mt], blo[nf]);
                    mma8(acc[mt][nf], alo[mt], bhi[nf]);
                }
        }
    }

    __syncthreads();

    float* lg = reinterpret_cast<float*>(smem_raw);
#pragma unroll
    for (int mt = 0; mt < 2; mt++)
#pragma unroll
        for (int nf = 0; nf < 4; nf++) {
            const int col = n0 + nf * 8 + 2 * tig;
            const int row = m0 + mt * 16 + gid;
            *reinterpret_cast<float2*>(lg + row * 66 + col) =
                make_float2(acc[mt][nf][0], acc[mt][nf][1]);
            *reinterpret_cast<float2*>(lg + (row + 8) * 66 + col) =
                make_float2(acc[mt][nf][2], acc[mt][nf][3]);
        }
    __syncthreads();

    if (tid < BM) {
        float* row = lg + tid * 66;
        float vals[TOPK + 1];
        int   idxs[TOPK + 1];
#pragma unroll
        for (int r = 0; r < TOPK + 1; r++) {       // top-9 for the gap check
            float best = -__int_as_float(0x7f800000);
            int bi = 0;
            for (int e = 0; e < N_EXP; e++) {
                float v = row[e];
                if (v > best) { best = v; bi = e; }
            }
            vals[r] = best;
            idxs[r] = bi;
            row[bi] = -__int_as_float(0x7f800000);
        }
        float mingap = vals[0] - vals[1];
#pragma unroll
        for (int r = 1; r < TOPK + 1 - 1; r++) mingap = fminf(mingap, vals[r] - vals[r + 1]);

        const long long gtok = block_m + tid;
        if (mingap < EPS) {     // ambiguous ranking -> exact recompute later
            int s = atomicAdd(&g_slow_count, 1);
            if (s < 16384) g_slow_tokens[s] = (int)gtok;
        }
        const float m0f = vals[0];
        float wv[TOPK];
        float s = 0.f;
#pragma unroll
        for (int r = 0; r < TOPK; r++) { wv[r] = __expf(vals[r] - m0f); s += wv[r]; }
        const float inv = 1.f / s;
#pragma unroll
        for (int r = 0; r < TOPK; r++) {
            out[gtok * TOPK + r] = wv[r] * inv;
            out[(long long)T * TOPK + gtok * TOPK + r] = (float)idxs[r];
        }
    }
}

// exact slow path: strict sequential-k fp32 (order matches reference per R1)
__global__ __launch_bounds__(64, 8)
void moe_gate_fixup(const float* __restrict__ X, const float* __restrict__ W,
                    float* __restrict__ out, int T) {
    __shared__ float lg[N_EXP];
    const int e = threadIdx.x;      // 64 threads = 64 experts
    const int n = g_slow_count < 16384 ? g_slow_count : 16384;

    for (int i = blockIdx.x; i < n; i += gridDim.x) {
        const int tok = g_slow_tokens[i];
        const float* x = X + (size_t)tok * H_DIM;
        const float* w = W + (size_t)e * H_DIM;
        float acc = 0.f;
#pragma unroll 4
        for (int k = 0; k < H_DIM; k += 4) {
            float4 xv = *reinterpret_cast<const float4*>(x + k);
            float4 wv = *reinterpret_cast<const float4*>(w + k);
            acc = fmaf(xv.x, wv.x, acc);   // strict sequential chain
            acc = fmaf(xv.y, wv.y, acc);
            acc = fmaf(xv.z, wv.z, acc);
            acc = fmaf(xv.w, wv.w, acc);
        }
        lg[e] = acc;
        __syncthreads();

        if (e == 0) {
            float vals[TOPK];
            int   idxs[TOPK];
#pragma unroll
            for (int r = 0; r < TOPK; r++) {
                float best = -__int_as_float(0x7f800000);
                int bi = 0;
                for (int q = 0; q < N_EXP; q++) {
                    float v = lg[q];
                    if (v > best) { best = v; bi = q; }
                }
                vals[r] = best;
                idxs[r] = bi;
                lg[bi] = -__int_as_float(0x7f800000);
            }
            const float m0f = vals[0];
            float wv[TOPK];
            float s = 0.f;
#pragma unroll
            for (int r = 0; r < TOPK; r++) { wv[r] = __expf(vals[r] - m0f); s += wv[r]; }
            const float inv = 1.f / s;
            const long long gtok = tok;
#pragma unroll
            for (int r = 0; r < TOPK; r++) {
                out[gtok * TOPK + r] = wv[r] * inv;
                out[(long long)T * TOPK + gtok * TOPK + r] = (float)idxs[r];
            }
        }
        __syncthreads();
    }
}

extern "C" void kernel_launch(void* const* d_in, const int* in_sizes, int n_in,
                              void* d_out, int out_size) {
    const float* X = (const float*)d_in[0];
    const float* W = (const float*)d_in[1];
    float* out = (float*)d_out;

    const int T = in_sizes[0] / H_DIM;   // 16384
    const int grid = T / BM;             // 128

    reset_kernel<<<1, 1>>>();
    cudaFuncSetAttribute(moe_gate_fast,
                         cudaFuncAttributeMaxDynamicSharedMemorySize, SMEM_BYTES);
    moe_gate_fast<<<grid, NTHREADS, SMEM_BYTES>>>(X, W, out, T);
    moe_gate_fixup<<<1024, 64>>>(X, W, out, T);
}